// round 12
// baseline (speedup 1.0000x reference)
#include <cuda_runtime.h>
#include <cstdint>
#include <cfloat>
#include <math.h>

#define KNN1    11            // top-11 including self (rank 0 = self, d2 = 0)
#define TPB     512
#define WARPS   16
#define PPB     32            // points per block (lane <-> point)
#define CH      32            // candidates per warp-chunk
#define BUFSZ   14            // trigger cnt>6, growth <=8/group -> max 14
#define TRIG    6
#define PREPTPB 256
#define MAXN    16384         // idx must fit 14 bits
#define MAXB    8
#define MAXPAIRS (MAXB*(MAXB-1)/2)
#define D2MASK  0xFFFFC000u
#define IDXMASK 0x3FFFu

__device__ float4   g_pos4[MAXN];     // xyz + 0.5*|c|^2
__device__ float4   g_norm4[MAXN];
__device__ float    g_acc[3];         // [0]=depth, [1]=normal, [2]=epipolar
__device__ unsigned g_done = 0;       // last-block ticket (reset in finalize)

// ---------------------------------------------------------------------------
__device__ __forceinline__ void camera_center(const float* V, float* C) {
    float m00 = V[0], m01 = V[1], m02 = V[2];
    float m10 = V[4], m11 = V[5], m12 = V[6];
    float m20 = V[8], m21 = V[9], m22 = V[10];
    float t0 = V[3], t1 = V[7], t2 = V[11];
    float c00 = m11 * m22 - m12 * m21;
    float c01 = m12 * m20 - m10 * m22;
    float c02 = m10 * m21 - m11 * m20;
    float id = 1.0f / (m00 * c00 + m01 * c01 + m02 * c02);
    float i00 = c00 * id, i01 = (m02 * m21 - m01 * m22) * id, i02 = (m01 * m12 - m02 * m11) * id;
    float i10 = c01 * id, i11 = (m00 * m22 - m02 * m20) * id, i12 = (m02 * m10 - m00 * m12) * id;
    float i20 = c02 * id, i21 = (m01 * m20 - m00 * m21) * id, i22 = (m00 * m11 - m01 * m10) * id;
    C[0] = -(i00 * t0 + i01 * t1 + i02 * t2);
    C[1] = -(i10 * t0 + i11 * t1 + i12 * t2);
    C[2] = -(i20 * t0 + i21 * t1 + i22 * t2);
}

__device__ __forceinline__ float warp_sum(float v) {
#pragma unroll
    for (int o = 16; o > 0; o >>= 1)
        v += __shfl_xor_sync(0xFFFFFFFFu, v, o);
    return v;
}

// ---------------------------------------------------------------------------
// Prep: one thread per (point, view-pair). Pair-0 lane additionally computes
// quaternion normal, packed position, and the depth term.
// ---------------------------------------------------------------------------
__global__ void __launch_bounds__(PREPTPB)
prep_kernel(const float* __restrict__ pos,
            const float* __restrict__ rot,
            const float* __restrict__ opac,
            const float* __restrict__ view,
            int N, int B, int Npad, int PP) {
    __shared__ float sV[MAXB * 16];
    __shared__ float sF[MAXPAIRS * 9];
    __shared__ float s_d, s_e;
    int tx = threadIdx.x;
    long long gid = (long long)blockIdx.x * PREPTPB + tx;
    int n  = (int)(gid / PP);
    int pr = (int)(gid % PP);

    if (tx == PREPTPB - 1) { s_d = 0.f; s_e = 0.f; }
    if (tx < B * 16) sV[tx] = view[tx];
    __syncthreads();

    if (tx < PP) {
        int q = tx, i = 0;
        while (q >= B - 1 - i) { q -= B - 1 - i; i++; }
        int j = i + 1 + q;
        const float* Vi = sV + i * 16;
        const float* Vj = sV + j * 16;
        float Ci[3], Cj[3];
        camera_center(Vi, Ci);
        camera_center(Vj, Cj);
        float txv = Cj[0] - Ci[0];
        float tyv = Cj[1] - Ci[1];
        float tzv = Cj[2] - Ci[2];
        float R[3][3];
        for (int r = 0; r < 3; r++)
            for (int c = 0; c < 3; c++)
                R[r][c] = Vj[r * 4 + 0] * Vi[c * 4 + 0]
                        + Vj[r * 4 + 1] * Vi[c * 4 + 1]
                        + Vj[r * 4 + 2] * Vi[c * 4 + 2];
        float* F = &sF[tx * 9];
        for (int c = 0; c < 3; c++) {
            F[0 * 3 + c] = -tzv * R[1][c] + tyv * R[2][c];
            F[1 * 3 + c] =  tzv * R[0][c] - txv * R[2][c];
            F[2 * 3 + c] = -tyv * R[0][c] + txv * R[1][c];
        }
    }
    __syncthreads();

    float dct = 0.f, ect = 0.f;
    if (n < N) {
        float px = pos[n * 3 + 0], py = pos[n * 3 + 1], pz = pos[n * 3 + 2];
        float op = opac[n];

        if (pr == 0) {
            float qw = rot[n * 4 + 0], qx = rot[n * 4 + 1];
            float qy = rot[n * 4 + 2], qz = rot[n * 4 + 3];
            float qn = 1.0f / sqrtf(qw * qw + qx * qx + qy * qy + qz * qz);
            qw *= qn; qx *= qn; qy *= qn; qz *= qn;
            float nx = 2.f * qx * qz + 2.f * qw * qy;
            float ny = 2.f * qy * qz - 2.f * qw * qx;
            float nz = 1.f - 2.f * qx * qx - 2.f * qy * qy;
            g_norm4[n] = make_float4(nx, ny, nz, 0.f);

            float sq = px * px + py * py + pz * pz;
            g_pos4[n] = make_float4(px, py, pz, 0.5f * sq);

            float prev = 0.f;
            for (int b = 0; b < B; b++) {
                const float* V = sV + b * 16;
                float cz = V[8] * px + V[9] * py + V[10] * pz + V[11];
                float wd = cz * op;
                if (b > 0) dct += fabsf(prev - wd);
                prev = wd;
            }
        }

        int q = pr, i = 0;
        while (q >= B - 1 - i) { q -= B - 1 - i; i++; }
        int j = i + 1 + q;
        const float* Vi = sV + i * 16;
        const float* Vj = sV + j * 16;
        float cxi = Vi[0] * px + Vi[1] * py + Vi[2]  * pz + Vi[3];
        float cyi = Vi[4] * px + Vi[5] * py + Vi[6]  * pz + Vi[7];
        float czi = Vi[8] * px + Vi[9] * py + Vi[10] * pz + Vi[11];
        float inv_i = 1.0f / fmaxf(czi, 1e-8f);
        float xi = cxi * inv_i, yi = cyi * inv_i;
        float cxj = Vj[0] * px + Vj[1] * py + Vj[2]  * pz + Vj[3];
        float cyj = Vj[4] * px + Vj[5] * py + Vj[6]  * pz + Vj[7];
        float czj = Vj[8] * px + Vj[9] * py + Vj[10] * pz + Vj[11];
        float inv_j = 1.0f / fmaxf(czj, 1e-8f);
        float xj = cxj * inv_j, yj = cyj * inv_j;

        const float* F = &sF[pr * 9];
        float l0 = F[0] * xi + F[1] * yi + F[2];
        float l1 = F[3] * xi + F[4] * yi + F[5];
        float l2 = F[6] * xi + F[7] * yi + F[8];
        float e = fabsf(xj * l0 + yj * l1 + l2);
        ect = op * e / (sqrtf(l0 * l0 + l1 * l1) + 1e-8f);
    } else if (n < Npad && pr == 0) {
        g_pos4[n] = make_float4(1e15f, 1e15f, 1e15f, 1e30f);  // sentinel pad
    }

    dct = warp_sum(dct);
    ect = warp_sum(ect);
    if ((tx & 31) == 0) {
        atomicAdd(&s_d, dct);
        atomicAdd(&s_e, ect);
    }
    __syncthreads();
    if (tx == 0) {
        atomicAdd(&g_acc[0], s_d);
        atomicAdd(&g_acc[2], s_e);
    }
}

// ---------------------------------------------------------------------------
// Flush helper: drain buffered candidate indices into the sorted top-11 key
// list, reloading positions from GLOBAL memory (L2-resident). Rare.
// ---------------------------------------------------------------------------
__device__ __forceinline__ void flush_buf(
    const uint32_t* __restrict__ bstart, int cnt,
    float4 me, float sq_p, uint32_t hk[KNN1], float& tau_m) {
    for (int i = 0; i < cnt; i++) {
        uint32_t idx = bstart[i * TPB];
        float4 c = __ldg(&g_pos4[idx]);
        float dx = me.x - c.x;
        float dy = me.y - c.y;
        float dz = me.z - c.z;
        float d2 = fmaf(dx, dx, fmaf(dy, dy, dz * dz));
        uint32_t v = (__float_as_uint(d2) & D2MASK) | idx;
        if (v < hk[KNN1 - 1]) {
#pragma unroll
            for (int q = 0; q < KNN1; q++) {
                uint32_t h = hk[q];
                bool sw = v < h;
                hk[q] = sw ? v : h;
                v     = sw ? h : v;
            }
        }
    }
    uint32_t worst = hk[KNN1 - 1];
    if (worst != 0xFFFFFFFFu) {
        // inflate quantized d2 by one quantum + eps: never reject a
        // candidate that could beat/tie the current 11th.
        float d2up = __uint_as_float((worst & D2MASK) + 0x4000u);
        tau_m = 0.5f * (d2up - sq_p) + 1e-6f;
    }
}

// ---------------------------------------------------------------------------
// KNN + normal loss + fused finalize. BARRIER-FREE main loop: each warp
// streams its own candidate range through a warp-private ping-pong chunk
// (coalesced LDG.128 -> STS -> syncwarp -> 32 broadcast LDS.128). Warps run
// fully decoupled; flushes never stall other warps. Hand-predicated STS in
// the hot loop (no branch, no wavefront when rejected).
// ---------------------------------------------------------------------------
__global__ void __launch_bounds__(TPB)
knn_kernel(const float* __restrict__ opac, float* __restrict__ out,
           int N, int B, int Npad) {
    __shared__ float4   s_ch[WARPS][2][CH];   // warp-private ping-pong chunks
    __shared__ uint32_t s_buf[BUFSZ * TPB];   // [slot][tid] -> bank = lane
    __shared__ float    s_nl;
    __shared__ int      s_last;

    int tid = threadIdx.x;
    int w   = tid >> 5;         // warp = candidate-range owner
    int l   = tid & 31;         // lane = point
    int p   = blockIdx.x * PPB + l;
    if (tid == 0) { s_nl = 0.f; s_last = 0; }

    int pc = (p < N) ? p : 0;
    float4 me = g_pos4[pc];
    float nmx = -me.x, nmy = -me.y, nmz = -me.z;
    float sq_p = 2.0f * me.w;

    uint32_t hk[KNN1];
#pragma unroll
    for (int q = 0; q < KNN1; q++) hk[q] = 0xFFFFFFFFu;
    float tau_m = FLT_MAX;

    uint32_t* bstart = s_buf + tid;
    uint32_t  baddr  = (uint32_t)__cvta_generic_to_shared(bstart);
    uint32_t  wp     = baddr;                           // shared-space write addr
    const uint32_t wtrig = baddr + (TRIG * TPB) * 4u;   // wp > wtrig <=> cnt > TRIG

    const int range = Npad / WARPS;      // Npad multiple of 512 -> multiple of CH
    const int cbeg  = w * range;
    const int nch   = range / CH;

    float4 cur = g_pos4[cbeg + l];       // lane-coalesced chunk load
    int phase = 0;

    for (int ch = 0; ch < nch; ch++) {
        int base = cbeg + ch * CH;
        float4 nxt = cur;
        if (ch + 1 < nch) nxt = g_pos4[base + CH + l];   // prefetch (LDG early)

        s_ch[w][phase][l] = cur;
        __syncwarp();
        const float4* tb = s_ch[w][phase];

#pragma unroll 1
        for (int g = 0; g < CH; g += 8) {
            int cbase = base + g;
#pragma unroll
            for (int k = 0; k < 8; k++) {
                float4 c = tb[g + k];                // broadcast LDS.128
                float m = fmaf(nmx, c.x, c.w);
                m = fmaf(nmy, c.y, m);
                m = fmaf(nmz, c.z, m);
                uint32_t idx = (uint32_t)(cbase + k);
                // predicated store + bump: no branch, no wavefront if rejected
                asm volatile(
                    "{\n\t"
                    ".reg .pred p;\n\t"
                    "setp.lt.f32 p, %1, %2;\n\t"
                    "@p st.shared.b32 [%0], %3;\n\t"
                    "@p add.u32 %0, %0, %4;\n\t"
                    "}"
                    : "+r"(wp)
                    : "f"(m), "f"(tau_m), "r"(idx), "n"(TPB * 4)
                    : "memory");
            }
            if (__ballot_sync(0xFFFFFFFFu, wp > wtrig)) {   // rare, warp-local
                int cnt = (int)((wp - baddr) >> 11);        // /(TPB*4)
                flush_buf(bstart, cnt, me, sq_p, hk, tau_m);
                wp = baddr;
            }
        }
        cur = nxt;
        phase ^= 1;
    }
    // final flush
    {
        int cnt = (int)((wp - baddr) >> 11);
        flush_buf(bstart, cnt, me, sq_p, hk, tau_m);
    }

    __syncthreads();
    // publish per-warp sorted lists: [rank][tid]
#pragma unroll
    for (int q = 0; q < KNN1; q++) s_buf[q * TPB + tid] = hk[q];
    __syncthreads();

    // 16-way merge: one thread per point (threads 0..31)
    if (tid < PPB) {
        int pp = blockIdx.x * PPB + tid;
        if (pp < N) {
            int head[WARPS];
#pragma unroll
            for (int u = 0; u < WARPS; u++) head[u] = 0;
            float4 nm = g_norm4[pp];
            float acc = 0.f;
            for (int r = 0; r < KNN1; r++) {
                uint32_t best = 0xFFFFFFFFu; int bw = 0;
#pragma unroll
                for (int u = 0; u < WARPS; u++) {
                    uint32_t v = (head[u] < KNN1)
                               ? s_buf[head[u] * TPB + u * 32 + tid]
                               : 0xFFFFFFFFu;
                    if (v < best) { best = v; bw = u; }
                }
#pragma unroll
                for (int u = 0; u < WARPS; u++) if (u == bw) head[u]++;
                if (r > 0) {   // rank 0 = self (d2 = 0)
                    int nb = (int)(best & IDXMASK);
                    float4 nn = g_norm4[nb];
                    acc += 1.0f - (nm.x * nn.x + nm.y * nn.y + nm.z * nn.z);
                }
            }
            atomicAdd(&s_nl, opac[pp] * (acc * (1.0f / (float)(KNN1 - 1))));
        }
    }
    __syncthreads();

    // block contribution + last-block fused finalize
    if (tid == 0) {
        atomicAdd(&g_acc[1], s_nl);
        __threadfence();
        unsigned ticket = atomicAdd(&g_done, 1u);
        if (ticket == gridDim.x - 1) s_last = 1;
    }
    __syncthreads();
    if (s_last && tid == 0) {
        int bm1 = (B - 1) < 1 ? 1 : (B - 1);
        int pairs = B * (B - 1) / 2; if (pairs < 1) pairs = 1;
        float depth  = g_acc[0] / ((float)N * (float)bm1);
        float normal = g_acc[1] / (float)N;
        float ep     = g_acc[2] / (float)pairs;
        out[0] = depth + normal + ep;
        g_acc[0] = 0.f; g_acc[1] = 0.f; g_acc[2] = 0.f;   // reset for replay
        g_done = 0u;
    }
}

// ---------------------------------------------------------------------------
extern "C" void kernel_launch(void* const* d_in, const int* in_sizes, int n_in,
                              void* d_out, int out_size) {
    const float* pos  = (const float*)d_in[0];
    const float* rot  = (const float*)d_in[1];
    const float* opac = (const float*)d_in[2];
    const float* view = (const float*)d_in[3];

    int N = in_sizes[0] / 3;
    int B = in_sizes[3] / 16;
    int PP = B * (B - 1) / 2; if (PP < 1) PP = 1;
    int Npad = ((N + 511) / 512) * 512;   // multiple of WARPS*CH

    long long totalPrep = (long long)Npad * PP;
    int prepBlocks = (int)((totalPrep + PREPTPB - 1) / PREPTPB);
    prep_kernel<<<prepBlocks, PREPTPB>>>(pos, rot, opac, view, N, B, Npad, PP);
    knn_kernel<<<(N + PPB - 1) / PPB, TPB>>>(opac, (float*)d_out, N, B, Npad);
}

// round 13
// speedup vs baseline: 1.0073x; 1.0073x over previous
#include <cuda_runtime.h>
#include <cstdint>
#include <cfloat>
#include <math.h>

#define KNN1    11            // top-11 including self (rank 0 = self, d2 = 0)
#define TPB     512
#define WARPS   16
#define PPB     32            // points per block (lane <-> point)
#define CH      32            // candidates per warp-chunk
#define BUFSZ   14            // trigger cnt>6, growth <=8/group -> max 14
#define TRIG    6
#define PREPTPB 256
#define MAXN    16384         // idx must fit 14 bits
#define MAXB    8
#define MAXPAIRS (MAXB*(MAXB-1)/2)
#define D2MASK  0xFFFFC000u
#define IDXMASK 0x3FFFu

__device__ float4   g_pos4[MAXN];     // xyz + 0.5*|c|^2
__device__ float4   g_norm4[MAXN];
__device__ float    g_acc[3];         // [0]=depth, [1]=normal, [2]=epipolar
__device__ unsigned g_done = 0;       // last-block ticket (reset in finalize)

// ---------------------------------------------------------------------------
__device__ __forceinline__ void camera_center(const float* V, float* C) {
    float m00 = V[0], m01 = V[1], m02 = V[2];
    float m10 = V[4], m11 = V[5], m12 = V[6];
    float m20 = V[8], m21 = V[9], m22 = V[10];
    float t0 = V[3], t1 = V[7], t2 = V[11];
    float c00 = m11 * m22 - m12 * m21;
    float c01 = m12 * m20 - m10 * m22;
    float c02 = m10 * m21 - m11 * m20;
    float id = 1.0f / (m00 * c00 + m01 * c01 + m02 * c02);
    float i00 = c00 * id, i01 = (m02 * m21 - m01 * m22) * id, i02 = (m01 * m12 - m02 * m11) * id;
    float i10 = c01 * id, i11 = (m00 * m22 - m02 * m20) * id, i12 = (m02 * m10 - m00 * m12) * id;
    float i20 = c02 * id, i21 = (m01 * m20 - m00 * m21) * id, i22 = (m00 * m11 - m01 * m10) * id;
    C[0] = -(i00 * t0 + i01 * t1 + i02 * t2);
    C[1] = -(i10 * t0 + i11 * t1 + i12 * t2);
    C[2] = -(i20 * t0 + i21 * t1 + i22 * t2);
}

__device__ __forceinline__ float warp_sum(float v) {
#pragma unroll
    for (int o = 16; o > 0; o >>= 1)
        v += __shfl_xor_sync(0xFFFFFFFFu, v, o);
    return v;
}

// ---------------------------------------------------------------------------
// Prep: one thread per (point, view-pair). Pair-0 lane additionally computes
// quaternion normal, packed position, and the depth term.
// ---------------------------------------------------------------------------
__global__ void __launch_bounds__(PREPTPB)
prep_kernel(const float* __restrict__ pos,
            const float* __restrict__ rot,
            const float* __restrict__ opac,
            const float* __restrict__ view,
            int N, int B, int Npad, int PP) {
    __shared__ float sV[MAXB * 16];
    __shared__ float sF[MAXPAIRS * 9];
    __shared__ float s_d, s_e;
    int tx = threadIdx.x;
    long long gid = (long long)blockIdx.x * PREPTPB + tx;
    int n  = (int)(gid / PP);
    int pr = (int)(gid % PP);

    if (tx == PREPTPB - 1) { s_d = 0.f; s_e = 0.f; }
    if (tx < B * 16) sV[tx] = view[tx];
    __syncthreads();

    if (tx < PP) {
        int q = tx, i = 0;
        while (q >= B - 1 - i) { q -= B - 1 - i; i++; }
        int j = i + 1 + q;
        const float* Vi = sV + i * 16;
        const float* Vj = sV + j * 16;
        float Ci[3], Cj[3];
        camera_center(Vi, Ci);
        camera_center(Vj, Cj);
        float txv = Cj[0] - Ci[0];
        float tyv = Cj[1] - Ci[1];
        float tzv = Cj[2] - Ci[2];
        float R[3][3];
        for (int r = 0; r < 3; r++)
            for (int c = 0; c < 3; c++)
                R[r][c] = Vj[r * 4 + 0] * Vi[c * 4 + 0]
                        + Vj[r * 4 + 1] * Vi[c * 4 + 1]
                        + Vj[r * 4 + 2] * Vi[c * 4 + 2];
        float* F = &sF[tx * 9];
        for (int c = 0; c < 3; c++) {
            F[0 * 3 + c] = -tzv * R[1][c] + tyv * R[2][c];
            F[1 * 3 + c] =  tzv * R[0][c] - txv * R[2][c];
            F[2 * 3 + c] = -tyv * R[0][c] + txv * R[1][c];
        }
    }
    __syncthreads();

    float dct = 0.f, ect = 0.f;
    if (n < N) {
        float px = pos[n * 3 + 0], py = pos[n * 3 + 1], pz = pos[n * 3 + 2];
        float op = opac[n];

        if (pr == 0) {
            float qw = rot[n * 4 + 0], qx = rot[n * 4 + 1];
            float qy = rot[n * 4 + 2], qz = rot[n * 4 + 3];
            float qn = 1.0f / sqrtf(qw * qw + qx * qx + qy * qy + qz * qz);
            qw *= qn; qx *= qn; qy *= qn; qz *= qn;
            float nx = 2.f * qx * qz + 2.f * qw * qy;
            float ny = 2.f * qy * qz - 2.f * qw * qx;
            float nz = 1.f - 2.f * qx * qx - 2.f * qy * qy;
            g_norm4[n] = make_float4(nx, ny, nz, 0.f);

            float sq = px * px + py * py + pz * pz;
            g_pos4[n] = make_float4(px, py, pz, 0.5f * sq);

            float prev = 0.f;
            for (int b = 0; b < B; b++) {
                const float* V = sV + b * 16;
                float cz = V[8] * px + V[9] * py + V[10] * pz + V[11];
                float wd = cz * op;
                if (b > 0) dct += fabsf(prev - wd);
                prev = wd;
            }
        }

        int q = pr, i = 0;
        while (q >= B - 1 - i) { q -= B - 1 - i; i++; }
        int j = i + 1 + q;
        const float* Vi = sV + i * 16;
        const float* Vj = sV + j * 16;
        float cxi = Vi[0] * px + Vi[1] * py + Vi[2]  * pz + Vi[3];
        float cyi = Vi[4] * px + Vi[5] * py + Vi[6]  * pz + Vi[7];
        float czi = Vi[8] * px + Vi[9] * py + Vi[10] * pz + Vi[11];
        float inv_i = 1.0f / fmaxf(czi, 1e-8f);
        float xi = cxi * inv_i, yi = cyi * inv_i;
        float cxj = Vj[0] * px + Vj[1] * py + Vj[2]  * pz + Vj[3];
        float cyj = Vj[4] * px + Vj[5] * py + Vj[6]  * pz + Vj[7];
        float czj = Vj[8] * px + Vj[9] * py + Vj[10] * pz + Vj[11];
        float inv_j = 1.0f / fmaxf(czj, 1e-8f);
        float xj = cxj * inv_j, yj = cyj * inv_j;

        const float* F = &sF[pr * 9];
        float l0 = F[0] * xi + F[1] * yi + F[2];
        float l1 = F[3] * xi + F[4] * yi + F[5];
        float l2 = F[6] * xi + F[7] * yi + F[8];
        float e = fabsf(xj * l0 + yj * l1 + l2);
        ect = op * e / (sqrtf(l0 * l0 + l1 * l1) + 1e-8f);
    } else if (n < Npad && pr == 0) {
        g_pos4[n] = make_float4(1e15f, 1e15f, 1e15f, 1e30f);  // sentinel pad
    }

    dct = warp_sum(dct);
    ect = warp_sum(ect);
    if ((tx & 31) == 0) {
        atomicAdd(&s_d, dct);
        atomicAdd(&s_e, ect);
    }
    __syncthreads();
    if (tx == 0) {
        atomicAdd(&g_acc[0], s_d);
        atomicAdd(&g_acc[2], s_e);
    }
}

// ---------------------------------------------------------------------------
// Flush helper: drain buffered candidate indices into the sorted top-11 key
// list, reloading positions from GLOBAL memory (L2-resident). Rare.
// ---------------------------------------------------------------------------
__device__ __forceinline__ void flush_buf(
    const uint32_t* __restrict__ bstart, int cnt,
    float4 me, float sq_p, uint32_t hk[KNN1], float& tau_m) {
    for (int i = 0; i < cnt; i++) {
        uint32_t idx = bstart[i * TPB];
        float4 c = __ldg(&g_pos4[idx]);
        float dx = me.x - c.x;
        float dy = me.y - c.y;
        float dz = me.z - c.z;
        float d2 = fmaf(dx, dx, fmaf(dy, dy, dz * dz));
        uint32_t v = (__float_as_uint(d2) & D2MASK) | idx;
        if (v < hk[KNN1 - 1]) {
#pragma unroll
            for (int q = 0; q < KNN1; q++) {
                uint32_t h = hk[q];
                bool sw = v < h;
                hk[q] = sw ? v : h;
                v     = sw ? h : v;
            }
        }
    }
    uint32_t worst = hk[KNN1 - 1];
    if (worst != 0xFFFFFFFFu) {
        // inflate quantized d2 by one quantum + eps: never reject a
        // candidate that could beat/tie the current 11th.
        float d2up = __uint_as_float((worst & D2MASK) + 0x4000u);
        tau_m = 0.5f * (d2up - sq_p) + 1e-6f;
    }
}

// ---------------------------------------------------------------------------
// KNN + normal loss + fused finalize. BARRIER-FREE main loop: each warp
// streams its own candidate range through a warp-private ping-pong chunk
// (coalesced LDG.128 -> STS -> syncwarp -> 32 broadcast LDS.128). Warps run
// fully decoupled; flushes never stall other warps. Hand-predicated STS in
// the hot loop (no branch, no wavefront when rejected).
// ---------------------------------------------------------------------------
__global__ void __launch_bounds__(TPB)
knn_kernel(const float* __restrict__ opac, float* __restrict__ out,
           int N, int B, int Npad) {
    __shared__ float4   s_ch[WARPS][2][CH];   // warp-private ping-pong chunks
    __shared__ uint32_t s_buf[BUFSZ * TPB];   // [slot][tid] -> bank = lane
    __shared__ float    s_nl;
    __shared__ int      s_last;

    int tid = threadIdx.x;
    int w   = tid >> 5;         // warp = candidate-range owner
    int l   = tid & 31;         // lane = point
    int p   = blockIdx.x * PPB + l;
    if (tid == 0) { s_nl = 0.f; s_last = 0; }

    int pc = (p < N) ? p : 0;
    float4 me = g_pos4[pc];
    float nmx = -me.x, nmy = -me.y, nmz = -me.z;
    float sq_p = 2.0f * me.w;

    uint32_t hk[KNN1];
#pragma unroll
    for (int q = 0; q < KNN1; q++) hk[q] = 0xFFFFFFFFu;
    float tau_m = FLT_MAX;

    uint32_t* bstart = s_buf + tid;
    uint32_t  baddr  = (uint32_t)__cvta_generic_to_shared(bstart);
    uint32_t  wp     = baddr;                           // shared-space write addr
    const uint32_t wtrig = baddr + (TRIG * TPB) * 4u;   // wp > wtrig <=> cnt > TRIG

    const int range = Npad / WARPS;      // Npad multiple of 512 -> multiple of CH
    const int cbeg  = w * range;
    const int nch   = range / CH;

    float4 cur = g_pos4[cbeg + l];       // lane-coalesced chunk load
    int phase = 0;

    for (int ch = 0; ch < nch; ch++) {
        int base = cbeg + ch * CH;
        float4 nxt = cur;
        if (ch + 1 < nch) nxt = g_pos4[base + CH + l];   // prefetch (LDG early)

        s_ch[w][phase][l] = cur;
        __syncwarp();
        const float4* tb = s_ch[w][phase];

#pragma unroll 1
        for (int g = 0; g < CH; g += 8) {
            int cbase = base + g;
#pragma unroll
            for (int k = 0; k < 8; k++) {
                float4 c = tb[g + k];                // broadcast LDS.128
                float m = fmaf(nmx, c.x, c.w);
                m = fmaf(nmy, c.y, m);
                m = fmaf(nmz, c.z, m);
                uint32_t idx = (uint32_t)(cbase + k);
                // predicated store + bump: no branch, no wavefront if rejected
                asm volatile(
                    "{\n\t"
                    ".reg .pred p;\n\t"
                    "setp.lt.f32 p, %1, %2;\n\t"
                    "@p st.shared.b32 [%0], %3;\n\t"
                    "@p add.u32 %0, %0, %4;\n\t"
                    "}"
                    : "+r"(wp)
                    : "f"(m), "f"(tau_m), "r"(idx), "n"(TPB * 4)
                    : "memory");
            }
            if (__ballot_sync(0xFFFFFFFFu, wp > wtrig)) {   // rare, warp-local
                int cnt = (int)((wp - baddr) >> 11);        // /(TPB*4)
                flush_buf(bstart, cnt, me, sq_p, hk, tau_m);
                wp = baddr;
            }
        }
        cur = nxt;
        phase ^= 1;
    }
    // final flush
    {
        int cnt = (int)((wp - baddr) >> 11);
        flush_buf(bstart, cnt, me, sq_p, hk, tau_m);
    }

    __syncthreads();
    // publish per-warp sorted lists: [rank][tid]
#pragma unroll
    for (int q = 0; q < KNN1; q++) s_buf[q * TPB + tid] = hk[q];
    __syncthreads();

    // 16-way merge: one thread per point (threads 0..31)
    if (tid < PPB) {
        int pp = blockIdx.x * PPB + tid;
        if (pp < N) {
            int head[WARPS];
#pragma unroll
            for (int u = 0; u < WARPS; u++) head[u] = 0;
            float4 nm = g_norm4[pp];
            float acc = 0.f;
            for (int r = 0; r < KNN1; r++) {
                uint32_t best = 0xFFFFFFFFu; int bw = 0;
#pragma unroll
                for (int u = 0; u < WARPS; u++) {
                    uint32_t v = (head[u] < KNN1)
                               ? s_buf[head[u] * TPB + u * 32 + tid]
                               : 0xFFFFFFFFu;
                    if (v < best) { best = v; bw = u; }
                }
#pragma unroll
                for (int u = 0; u < WARPS; u++) if (u == bw) head[u]++;
                if (r > 0) {   // rank 0 = self (d2 = 0)
                    int nb = (int)(best & IDXMASK);
                    float4 nn = g_norm4[nb];
                    acc += 1.0f - (nm.x * nn.x + nm.y * nn.y + nm.z * nn.z);
                }
            }
            atomicAdd(&s_nl, opac[pp] * (acc * (1.0f / (float)(KNN1 - 1))));
        }
    }
    __syncthreads();

    // block contribution + last-block fused finalize
    if (tid == 0) {
        atomicAdd(&g_acc[1], s_nl);
        __threadfence();
        unsigned ticket = atomicAdd(&g_done, 1u);
        if (ticket == gridDim.x - 1) s_last = 1;
    }
    __syncthreads();
    if (s_last && tid == 0) {
        int bm1 = (B - 1) < 1 ? 1 : (B - 1);
        int pairs = B * (B - 1) / 2; if (pairs < 1) pairs = 1;
        float depth  = g_acc[0] / ((float)N * (float)bm1);
        float normal = g_acc[1] / (float)N;
        float ep     = g_acc[2] / (float)pairs;
        out[0] = depth + normal + ep;
        g_acc[0] = 0.f; g_acc[1] = 0.f; g_acc[2] = 0.f;   // reset for replay
        g_done = 0u;
    }
}

// ---------------------------------------------------------------------------
extern "C" void kernel_launch(void* const* d_in, const int* in_sizes, int n_in,
                              void* d_out, int out_size) {
    const float* pos  = (const float*)d_in[0];
    const float* rot  = (const float*)d_in[1];
    const float* opac = (const float*)d_in[2];
    const float* view = (const float*)d_in[3];

    int N = in_sizes[0] / 3;
    int B = in_sizes[3] / 16;
    int PP = B * (B - 1) / 2; if (PP < 1) PP = 1;
    int Npad = ((N + 511) / 512) * 512;   // multiple of WARPS*CH

    long long totalPrep = (long long)Npad * PP;
    int prepBlocks = (int)((totalPrep + PREPTPB - 1) / PREPTPB);
    prep_kernel<<<prepBlocks, PREPTPB>>>(pos, rot, opac, view, N, B, Npad, PP);
    knn_kernel<<<(N + PPB - 1) / PPB, TPB>>>(opac, (float*)d_out, N, B, Npad);
}

// round 14
// speedup vs baseline: 1.0118x; 1.0045x over previous
#include <cuda_runtime.h>
#include <cstdint>
#include <cfloat>
#include <math.h>

#define KNN1    11            // top-11 including self (rank 0 = self, d2 = 0)
#define TPB     512
#define WARPS   16
#define PPB     32            // points per block (lane <-> point)
#define CH      32            // candidates per warp-chunk
#define BUFSZ   14            // trigger cnt>6, growth <=8/group -> max 14
#define TRIG    6
#define PREPTPB 256
#define MAXN    16384         // idx must fit 14 bits
#define MAXB    8
#define MAXPAIRS (MAXB*(MAXB-1)/2)
#define D2MASK  0xFFFFC000u
#define IDXMASK 0x3FFFu

__device__ float4   g_pos4[MAXN];     // xyz + 0.5*|c|^2
__device__ float4   g_norm4[MAXN];
__device__ float    g_acc[3];         // [0]=depth, [1]=normal, [2]=epipolar
__device__ unsigned g_done = 0;       // last-block ticket (reset in finalize)

// ---------------------------------------------------------------------------
__device__ __forceinline__ void camera_center(const float* V, float* C) {
    float m00 = V[0], m01 = V[1], m02 = V[2];
    float m10 = V[4], m11 = V[5], m12 = V[6];
    float m20 = V[8], m21 = V[9], m22 = V[10];
    float t0 = V[3], t1 = V[7], t2 = V[11];
    float c00 = m11 * m22 - m12 * m21;
    float c01 = m12 * m20 - m10 * m22;
    float c02 = m10 * m21 - m11 * m20;
    float id = 1.0f / (m00 * c00 + m01 * c01 + m02 * c02);
    float i00 = c00 * id, i01 = (m02 * m21 - m01 * m22) * id, i02 = (m01 * m12 - m02 * m11) * id;
    float i10 = c01 * id, i11 = (m00 * m22 - m02 * m20) * id, i12 = (m02 * m10 - m00 * m12) * id;
    float i20 = c02 * id, i21 = (m01 * m20 - m00 * m21) * id, i22 = (m00 * m11 - m01 * m10) * id;
    C[0] = -(i00 * t0 + i01 * t1 + i02 * t2);
    C[1] = -(i10 * t0 + i11 * t1 + i12 * t2);
    C[2] = -(i20 * t0 + i21 * t1 + i22 * t2);
}

__device__ __forceinline__ float warp_sum(float v) {
#pragma unroll
    for (int o = 16; o > 0; o >>= 1)
        v += __shfl_xor_sync(0xFFFFFFFFu, v, o);
    return v;
}

// ---------------------------------------------------------------------------
// Prep: one thread per (point, view-pair). Pair-0 lane additionally computes
// quaternion normal, packed position, and the depth term.
// ---------------------------------------------------------------------------
__global__ void __launch_bounds__(PREPTPB)
prep_kernel(const float* __restrict__ pos,
            const float* __restrict__ rot,
            const float* __restrict__ opac,
            const float* __restrict__ view,
            int N, int B, int Npad, int PP) {
    __shared__ float sV[MAXB * 16];
    __shared__ float sF[MAXPAIRS * 9];
    __shared__ float s_d, s_e;
    int tx = threadIdx.x;
    long long gid = (long long)blockIdx.x * PREPTPB + tx;
    int n  = (int)(gid / PP);
    int pr = (int)(gid % PP);

    if (tx == PREPTPB - 1) { s_d = 0.f; s_e = 0.f; }
    if (tx < B * 16) sV[tx] = view[tx];
    __syncthreads();

    if (tx < PP) {
        int q = tx, i = 0;
        while (q >= B - 1 - i) { q -= B - 1 - i; i++; }
        int j = i + 1 + q;
        const float* Vi = sV + i * 16;
        const float* Vj = sV + j * 16;
        float Ci[3], Cj[3];
        camera_center(Vi, Ci);
        camera_center(Vj, Cj);
        float txv = Cj[0] - Ci[0];
        float tyv = Cj[1] - Ci[1];
        float tzv = Cj[2] - Ci[2];
        float R[3][3];
        for (int r = 0; r < 3; r++)
            for (int c = 0; c < 3; c++)
                R[r][c] = Vj[r * 4 + 0] * Vi[c * 4 + 0]
                        + Vj[r * 4 + 1] * Vi[c * 4 + 1]
                        + Vj[r * 4 + 2] * Vi[c * 4 + 2];
        float* F = &sF[tx * 9];
        for (int c = 0; c < 3; c++) {
            F[0 * 3 + c] = -tzv * R[1][c] + tyv * R[2][c];
            F[1 * 3 + c] =  tzv * R[0][c] - txv * R[2][c];
            F[2 * 3 + c] = -tyv * R[0][c] + txv * R[1][c];
        }
    }
    __syncthreads();

    float dct = 0.f, ect = 0.f;
    if (n < N) {
        float px = pos[n * 3 + 0], py = pos[n * 3 + 1], pz = pos[n * 3 + 2];
        float op = opac[n];

        if (pr == 0) {
            float qw = rot[n * 4 + 0], qx = rot[n * 4 + 1];
            float qy = rot[n * 4 + 2], qz = rot[n * 4 + 3];
            float qn = 1.0f / sqrtf(qw * qw + qx * qx + qy * qy + qz * qz);
            qw *= qn; qx *= qn; qy *= qn; qz *= qn;
            float nx = 2.f * qx * qz + 2.f * qw * qy;
            float ny = 2.f * qy * qz - 2.f * qw * qx;
            float nz = 1.f - 2.f * qx * qx - 2.f * qy * qy;
            g_norm4[n] = make_float4(nx, ny, nz, 0.f);

            float sq = px * px + py * py + pz * pz;
            g_pos4[n] = make_float4(px, py, pz, 0.5f * sq);

            float prev = 0.f;
            for (int b = 0; b < B; b++) {
                const float* V = sV + b * 16;
                float cz = V[8] * px + V[9] * py + V[10] * pz + V[11];
                float wd = cz * op;
                if (b > 0) dct += fabsf(prev - wd);
                prev = wd;
            }
        }

        int q = pr, i = 0;
        while (q >= B - 1 - i) { q -= B - 1 - i; i++; }
        int j = i + 1 + q;
        const float* Vi = sV + i * 16;
        const float* Vj = sV + j * 16;
        float cxi = Vi[0] * px + Vi[1] * py + Vi[2]  * pz + Vi[3];
        float cyi = Vi[4] * px + Vi[5] * py + Vi[6]  * pz + Vi[7];
        float czi = Vi[8] * px + Vi[9] * py + Vi[10] * pz + Vi[11];
        float inv_i = 1.0f / fmaxf(czi, 1e-8f);
        float xi = cxi * inv_i, yi = cyi * inv_i;
        float cxj = Vj[0] * px + Vj[1] * py + Vj[2]  * pz + Vj[3];
        float cyj = Vj[4] * px + Vj[5] * py + Vj[6]  * pz + Vj[7];
        float czj = Vj[8] * px + Vj[9] * py + Vj[10] * pz + Vj[11];
        float inv_j = 1.0f / fmaxf(czj, 1e-8f);
        float xj = cxj * inv_j, yj = cyj * inv_j;

        const float* F = &sF[pr * 9];
        float l0 = F[0] * xi + F[1] * yi + F[2];
        float l1 = F[3] * xi + F[4] * yi + F[5];
        float l2 = F[6] * xi + F[7] * yi + F[8];
        float e = fabsf(xj * l0 + yj * l1 + l2);
        ect = op * e / (sqrtf(l0 * l0 + l1 * l1) + 1e-8f);
    } else if (n < Npad && pr == 0) {
        g_pos4[n] = make_float4(1e15f, 1e15f, 1e15f, 1e30f);  // sentinel pad
    }

    dct = warp_sum(dct);
    ect = warp_sum(ect);
    if ((tx & 31) == 0) {
        atomicAdd(&s_d, dct);
        atomicAdd(&s_e, ect);
    }
    __syncthreads();
    if (tx == 0) {
        atomicAdd(&g_acc[0], s_d);
        atomicAdd(&g_acc[2], s_e);
    }
}

// ---------------------------------------------------------------------------
// Flush helper: drain buffered candidate indices into the sorted top-11 key
// list, reloading positions from GLOBAL memory (L2-resident). Rare.
// ---------------------------------------------------------------------------
__device__ __forceinline__ void flush_buf(
    const uint32_t* __restrict__ bstart, int cnt,
    float4 me, float sq_p, uint32_t hk[KNN1], float& tau_m) {
    for (int i = 0; i < cnt; i++) {
        uint32_t idx = bstart[i * TPB];
        float4 c = __ldg(&g_pos4[idx]);
        float dx = me.x - c.x;
        float dy = me.y - c.y;
        float dz = me.z - c.z;
        float d2 = fmaf(dx, dx, fmaf(dy, dy, dz * dz));
        uint32_t v = (__float_as_uint(d2) & D2MASK) | idx;
        if (v < hk[KNN1 - 1]) {
#pragma unroll
            for (int q = 0; q < KNN1; q++) {
                uint32_t h = hk[q];
                bool sw = v < h;
                hk[q] = sw ? v : h;
                v     = sw ? h : v;
            }
        }
    }
    uint32_t worst = hk[KNN1 - 1];
    if (worst != 0xFFFFFFFFu) {
        // inflate quantized d2 by one quantum + eps: never reject a
        // candidate that could beat/tie the current 11th.
        float d2up = __uint_as_float((worst & D2MASK) + 0x4000u);
        tau_m = 0.5f * (d2up - sq_p) + 1e-6f;
    }
}

// ---------------------------------------------------------------------------
// KNN + normal loss + fused finalize. BARRIER-FREE main loop: each warp
// streams its own candidate range through a warp-private ping-pong chunk
// (coalesced LDG.128 -> STS -> syncwarp -> 32 broadcast LDS.128). Warps run
// fully decoupled; flushes never stall other warps. Hand-predicated STS in
// the hot loop (no branch, no wavefront when rejected).
// ---------------------------------------------------------------------------
__global__ void __launch_bounds__(TPB)
knn_kernel(const float* __restrict__ opac, float* __restrict__ out,
           int N, int B, int Npad) {
    __shared__ float4   s_ch[WARPS][2][CH];   // warp-private ping-pong chunks
    __shared__ uint32_t s_buf[BUFSZ * TPB];   // [slot][tid] -> bank = lane
    __shared__ float    s_nl;
    __shared__ int      s_last;

    int tid = threadIdx.x;
    int w   = tid >> 5;         // warp = candidate-range owner
    int l   = tid & 31;         // lane = point
    int p   = blockIdx.x * PPB + l;
    if (tid == 0) { s_nl = 0.f; s_last = 0; }

    int pc = (p < N) ? p : 0;
    float4 me = g_pos4[pc];
    float nmx = -me.x, nmy = -me.y, nmz = -me.z;
    float sq_p = 2.0f * me.w;

    uint32_t hk[KNN1];
#pragma unroll
    for (int q = 0; q < KNN1; q++) hk[q] = 0xFFFFFFFFu;
    float tau_m = FLT_MAX;

    uint32_t* bstart = s_buf + tid;
    uint32_t  baddr  = (uint32_t)__cvta_generic_to_shared(bstart);
    uint32_t  wp     = baddr;                           // shared-space write addr
    const uint32_t wtrig = baddr + (TRIG * TPB) * 4u;   // wp > wtrig <=> cnt > TRIG

    const int range = Npad / WARPS;      // Npad multiple of 512 -> multiple of CH
    const int cbeg  = w * range;
    const int nch   = range / CH;

    float4 cur = g_pos4[cbeg + l];       // lane-coalesced chunk load
    int phase = 0;

    for (int ch = 0; ch < nch; ch++) {
        int base = cbeg + ch * CH;
        float4 nxt = cur;
        if (ch + 1 < nch) nxt = g_pos4[base + CH + l];   // prefetch (LDG early)

        s_ch[w][phase][l] = cur;
        __syncwarp();
        const float4* tb = s_ch[w][phase];

#pragma unroll 1
        for (int g = 0; g < CH; g += 8) {
            int cbase = base + g;
#pragma unroll
            for (int k = 0; k < 8; k++) {
                float4 c = tb[g + k];                // broadcast LDS.128
                float m = fmaf(nmx, c.x, c.w);
                m = fmaf(nmy, c.y, m);
                m = fmaf(nmz, c.z, m);
                uint32_t idx = (uint32_t)(cbase + k);
                // predicated store + bump: no branch, no wavefront if rejected
                asm volatile(
                    "{\n\t"
                    ".reg .pred p;\n\t"
                    "setp.lt.f32 p, %1, %2;\n\t"
                    "@p st.shared.b32 [%0], %3;\n\t"
                    "@p add.u32 %0, %0, %4;\n\t"
                    "}"
                    : "+r"(wp)
                    : "f"(m), "f"(tau_m), "r"(idx), "n"(TPB * 4)
                    : "memory");
            }
            if (__ballot_sync(0xFFFFFFFFu, wp > wtrig)) {   // rare, warp-local
                int cnt = (int)((wp - baddr) >> 11);        // /(TPB*4)
                flush_buf(bstart, cnt, me, sq_p, hk, tau_m);
                wp = baddr;
            }
        }
        cur = nxt;
        phase ^= 1;
    }
    // final flush
    {
        int cnt = (int)((wp - baddr) >> 11);
        flush_buf(bstart, cnt, me, sq_p, hk, tau_m);
    }

    __syncthreads();
    // publish per-warp sorted lists: [rank][tid]
#pragma unroll
    for (int q = 0; q < KNN1; q++) s_buf[q * TPB + tid] = hk[q];
    __syncthreads();

    // 16-way merge: one thread per point (threads 0..31)
    if (tid < PPB) {
        int pp = blockIdx.x * PPB + tid;
        if (pp < N) {
            int head[WARPS];
#pragma unroll
            for (int u = 0; u < WARPS; u++) head[u] = 0;
            float4 nm = g_norm4[pp];
            float acc = 0.f;
            for (int r = 0; r < KNN1; r++) {
                uint32_t best = 0xFFFFFFFFu; int bw = 0;
#pragma unroll
                for (int u = 0; u < WARPS; u++) {
                    uint32_t v = (head[u] < KNN1)
                               ? s_buf[head[u] * TPB + u * 32 + tid]
                               : 0xFFFFFFFFu;
                    if (v < best) { best = v; bw = u; }
                }
#pragma unroll
                for (int u = 0; u < WARPS; u++) if (u == bw) head[u]++;
                if (r > 0) {   // rank 0 = self (d2 = 0)
                    int nb = (int)(best & IDXMASK);
                    float4 nn = g_norm4[nb];
                    acc += 1.0f - (nm.x * nn.x + nm.y * nn.y + nm.z * nn.z);
                }
            }
            atomicAdd(&s_nl, opac[pp] * (acc * (1.0f / (float)(KNN1 - 1))));
        }
    }
    __syncthreads();

    // block contribution + last-block fused finalize
    if (tid == 0) {
        atomicAdd(&g_acc[1], s_nl);
        __threadfence();
        unsigned ticket = atomicAdd(&g_done, 1u);
        if (ticket == gridDim.x - 1) s_last = 1;
    }
    __syncthreads();
    if (s_last && tid == 0) {
        int bm1 = (B - 1) < 1 ? 1 : (B - 1);
        int pairs = B * (B - 1) / 2; if (pairs < 1) pairs = 1;
        float depth  = g_acc[0] / ((float)N * (float)bm1);
        float normal = g_acc[1] / (float)N;
        float ep     = g_acc[2] / (float)pairs;
        out[0] = depth + normal + ep;
        g_acc[0] = 0.f; g_acc[1] = 0.f; g_acc[2] = 0.f;   // reset for replay
        g_done = 0u;
    }
}

// ---------------------------------------------------------------------------
extern "C" void kernel_launch(void* const* d_in, const int* in_sizes, int n_in,
                              void* d_out, int out_size) {
    const float* pos  = (const float*)d_in[0];
    const float* rot  = (const float*)d_in[1];
    const float* opac = (const float*)d_in[2];
    const float* view = (const float*)d_in[3];

    int N = in_sizes[0] / 3;
    int B = in_sizes[3] / 16;
    int PP = B * (B - 1) / 2; if (PP < 1) PP = 1;
    int Npad = ((N + 511) / 512) * 512;   // multiple of WARPS*CH

    long long totalPrep = (long long)Npad * PP;
    int prepBlocks = (int)((totalPrep + PREPTPB - 1) / PREPTPB);
    prep_kernel<<<prepBlocks, PREPTPB>>>(pos, rot, opac, view, N, B, Npad, PP);
    knn_kernel<<<(N + PPB - 1) / PPB, TPB>>>(opac, (float*)d_out, N, B, Npad);
}